// round 4
// baseline (speedup 1.0000x reference)
#include <cuda_runtime.h>
#include <cstdint>

#define NBLK 8
#define CH 256
#define ROWSTRIDE 2048
#define OUT_HALF 33554432u

// stage: A_r 16KB | A_i 16KB | W_r 8KB | W_i 8KB  = 48KB
#define OFF_AR 0
#define OFF_AI 16384
#define OFF_WR 32768
#define OFF_WI 40960
#define STAGE_BYTES 49152
#define SMEM_ST0  2048
#define SMEM_ALLOC (2048 + 2*STAGE_BYTES)   // 100352 -> 2 CTA/SM

// weights, K-major, tf32-RNA, fragment-permuted:
// g_wT[sel][blk][n][p],  p(k) = (k&3)*64 + (k>>3)*2 + ((k>>2)&1)
__device__ float g_wT[2*NBLK*CH*CH];

// ---------------------------------------------------------------------------
__device__ __forceinline__ uint32_t smem_u32(const void* p){
    uint32_t r;
    asm("{ .reg .u64 t; cvta.to.shared.u64 t, %1; cvt.u32.u64 %0, t; }"
        : "=r"(r) : "l"(p));
    return r;
}
__device__ __forceinline__ void cpa16(uint32_t dst, const float* src){
    asm volatile("cp.async.cg.shared.global [%0], [%1], 16;"
                 :: "r"(dst), "l"(src) : "memory");
}
__device__ __forceinline__ void cp_commit(){ asm volatile("cp.async.commit_group;" ::: "memory"); }
__device__ __forceinline__ void cp_wait1(){ asm volatile("cp.async.wait_group 1;" ::: "memory"); }
__device__ __forceinline__ void cp_wait0(){ asm volatile("cp.async.wait_group 0;" ::: "memory"); }

__device__ __forceinline__ float lds_f(uint32_t a){
    float v; asm volatile("ld.shared.f32 %0, [%1];" : "=f"(v) : "r"(a)); return v;
}
__device__ __forceinline__ void lds128(uint32_t a, uint32_t* v){
    asm volatile("ld.shared.v4.b32 {%0,%1,%2,%3}, [%4];"
        : "=r"(v[0]), "=r"(v[1]), "=r"(v[2]), "=r"(v[3]) : "r"(a));
}
__device__ __forceinline__ uint32_t f2tf(float v){
    uint32_t r; asm("cvt.rna.tf32.f32 %0, %1;" : "=r"(r) : "f"(v)); return r;
}
__device__ __forceinline__ void mma8(float* d, const uint32_t* a,
                                     uint32_t b0, uint32_t b1){
    asm volatile(
        "mma.sync.aligned.m16n8k8.row.col.f32.tf32.tf32.f32 "
        "{%0,%1,%2,%3}, {%4,%5,%6,%7}, {%8,%9}, {%0,%1,%2,%3};"
        : "+f"(d[0]), "+f"(d[1]), "+f"(d[2]), "+f"(d[3])
        : "r"(a[0]), "r"(a[1]), "r"(a[2]), "r"(a[3]), "r"(b0), "r"(b1));
}

// ---------------------------------------------------------------------------
// Prep: w[b][d][n] -> g_wT[sel][b][n][p(d)], RNA-rounded to tf32
// ---------------------------------------------------------------------------
__global__ void emm_prep(const float* __restrict__ wr, const float* __restrict__ wi){
    __shared__ float tile[32][33];
    int bb = blockIdx.z;                 // sel*8 + b
    int b = bb & 7, sel = bb >> 3;
    const float* s = (sel ? wi : wr) + (size_t)b*CH*CH;
    float* dst = g_wT + ((size_t)bb*CH)*CH;
    int d0 = blockIdx.x*32, n0 = blockIdx.y*32;
    int tx = threadIdx.x, ty = threadIdx.y;
    #pragma unroll
    for (int i = 0; i < 32; i += 8)
        tile[ty+i][tx] = s[(size_t)(d0+ty+i)*CH + (n0+tx)];   // [d][n]
    __syncthreads();
    // write: lane tx = j (d-offset), row = n-offset (ty+i)
    int q = tx & 3, u = tx >> 2;
    int pbase = q*64 + (d0 >> 2) + u;
    #pragma unroll
    for (int i = 0; i < 32; i += 8){
        uint32_t r; asm("cvt.rna.tf32.f32 %0, %1;" : "=r"(r) : "f"(tile[tx][ty+i]));
        dst[(size_t)(n0+ty+i)*CH + pbase] = __uint_as_float(r);
    }
}

// ---------------------------------------------------------------------------
// Stage load: A 128x32 (r,i), W 64x32 permuted (r,i); k0 = kk*32
// ---------------------------------------------------------------------------
__device__ __forceinline__ void load_stage(
    const float* __restrict__ xr, const float* __restrict__ xi,
    uint32_t st, int m0, int blk, int n0, int k0, int tid)
{
    const float* wr = g_wT + ((size_t)blk*CH + n0)*CH;
    const float* wi = g_wT + ((size_t)(NBLK + blk)*CH + n0)*CH;
    #pragma unroll
    for (int i = 0; i < 4; i++){            // A: 1024 chunks each tensor
        int c = tid + i*256;
        int row = c >> 3, cc = c & 7;
        uint32_t d = st + (uint32_t)(row*128 + ((cc ^ (row & 7))*16));
        size_t g = (size_t)(m0 + row)*ROWSTRIDE + blk*CH + k0 + cc*4;
        cpa16(d + OFF_AR, xr + g);
        cpa16(d + OFF_AI, xi + g);
    }
    {                                        // W: 512 chunks each tensor
        int c = tid, row = c >> 3, cc = c & 7;
        uint32_t d = st + (uint32_t)(row*128 + ((cc ^ (row & 7))*16));
        size_t g = (size_t)row*CH + (cc >> 1)*64 + (k0 >> 2) + (cc & 1)*4;
        cpa16(d + OFF_WR, wr + g);
        cpa16(d + OFF_WI, wi + g);
        c = tid + 256; row = c >> 3; cc = c & 7;
        d = st + (uint32_t)(row*128 + ((cc ^ (row & 7))*16));
        g = (size_t)row*CH + (cc >> 1)*64 + (k0 >> 2) + (cc & 1)*4;
        cpa16(d + OFF_WR, wr + g);
        cpa16(d + OFF_WI, wi + g);
    }
}

// ---------------------------------------------------------------------------
__global__ void __launch_bounds__(256, 2) emm_main(
    const float* __restrict__ xr, const float* __restrict__ xi,
    const float* __restrict__ br, const float* __restrict__ bi,
    float* __restrict__ out)
{
    extern __shared__ char smem[];
    uint32_t sb = smem_u32(smem);
    int tid = threadIdx.x;
    int wid = tid >> 5, lid = tid & 31;
    int g = lid >> 2, t = lid & 3;

    int bx = blockIdx.x;
    int m0 = (bx >> 2) * 128;
    int n0 = (bx & 3) * 64;
    int blk = blockIdx.y;

    float* bs = (float*)smem;               // bias: 512 floats
    bs[tid]       = br[blk*CH + tid];
    bs[tid + 256] = bi[blk*CH + tid];

    uint32_t st0 = sb + SMEM_ST0;
    uint32_t st1 = st0 + STAGE_BYTES;

    float dr[8][4], di[8][4];
    #pragma unroll
    for (int n = 0; n < 8; n++)
        #pragma unroll
        for (int c = 0; c < 4; c++){ dr[n][c] = 0.f; di[n][c] = 0.f; }

    load_stage(xr, xi, st0, m0, blk, n0, 0,  tid); cp_commit();
    load_stage(xr, xi, st1, m0, blk, n0, 32, tid); cp_commit();

    int rA = wid*16 + g;                     // rA & 7 == g, (rA+8) & 7 == g
    uint32_t aoffA = (uint32_t)(rA*128 + t*4);
    uint32_t aoffB = aoffA + 8*128;

    #pragma unroll 1
    for (int kk = 0; kk < 8; kk++){
        uint32_t st = (kk & 1) ? st1 : st0;
        if (kk == 7) cp_wait0(); else cp_wait1();
        __syncthreads();

        uint32_t aA = st + aoffA, aB = st + aoffB;

        #pragma unroll
        for (int sp = 0; sp < 2; sp++){
            int x0 = sp*4;
            uint32_t o0 = (uint32_t)(((x0    ) ^ g) << 4);
            uint32_t o1 = (uint32_t)(((x0 + 1) ^ g) << 4);
            uint32_t o2 = (uint32_t)(((x0 + 2) ^ g) << 4);
            uint32_t o3 = (uint32_t)(((x0 + 3) ^ g) << 4);
            uint32_t far0[4], fai0[4], far1[4], fai1[4];
            far0[0] = f2tf(lds_f(aA + OFF_AR + o0));
            far0[1] = f2tf(lds_f(aB + OFF_AR + o0));
            far0[2] = f2tf(lds_f(aA + OFF_AR + o1));
            far0[3] = f2tf(lds_f(aB + OFF_AR + o1));
            fai0[0] = f2tf(lds_f(aA + OFF_AI + o0));
            fai0[1] = f2tf(lds_f(aB + OFF_AI + o0));
            fai0[2] = f2tf(lds_f(aA + OFF_AI + o1));
            fai0[3] = f2tf(lds_f(aB + OFF_AI + o1));
            far1[0] = f2tf(lds_f(aA + OFF_AR + o2));
            far1[1] = f2tf(lds_f(aB + OFF_AR + o2));
            far1[2] = f2tf(lds_f(aA + OFF_AR + o3));
            far1[3] = f2tf(lds_f(aB + OFF_AR + o3));
            fai1[0] = f2tf(lds_f(aA + OFF_AI + o2));
            fai1[1] = f2tf(lds_f(aB + OFF_AI + o2));
            fai1[2] = f2tf(lds_f(aA + OFF_AI + o3));
            fai1[3] = f2tf(lds_f(aB + OFF_AI + o3));

            uint32_t co = (uint32_t)((((t*2 + sp) ^ g) << 4));
            uint32_t wrb = st + OFF_WR + (uint32_t)(g*128) + co;
            uint32_t wib = st + OFF_WI + (uint32_t)(g*128) + co;

            uint32_t b0r[4], b0i[4], b1r[4], b1i[4];
            lds128(wrb, b0r); lds128(wib, b0i);
            #pragma unroll
            for (int nn = 0; nn < 8; nn += 2){
                lds128(wrb + (nn+1)*1024, b1r);
                lds128(wib + (nn+1)*1024, b1i);
                // s even
                mma8(di[nn], far0, b0i[0], b0i[1]);
                mma8(di[nn], fai0, b0r[0], b0r[1]);
                mma8(dr[nn], far0, b0r[0], b0r[1]);
                b0i[0] ^= 0x80000000u; b0i[1] ^= 0x80000000u;
                mma8(dr[nn], fai0, b0i[0], b0i[1]);
                // s odd
                mma8(di[nn], far1, b0i[2], b0i[3]);
                mma8(di[nn], fai1, b0r[2], b0r[3]);
                mma8(dr[nn], far1, b0r[2], b0r[3]);
                b0i[2] ^= 0x80000000u; b0i[3] ^= 0x80000000u;
                mma8(dr[nn], fai1, b0i[2], b0i[3]);

                if (nn + 2 < 8){
                    lds128(wrb + (nn+2)*1024, b0r);
                    lds128(wib + (nn+2)*1024, b0i);
                }
                mma8(di[nn+1], far0, b1i[0], b1i[1]);
                mma8(di[nn+1], fai0, b1r[0], b1r[1]);
                mma8(dr[nn+1], far0, b1r[0], b1r[1]);
                b1i[0] ^= 0x80000000u; b1i[1] ^= 0x80000000u;
                mma8(dr[nn+1], fai0, b1i[0], b1i[1]);
                mma8(di[nn+1], far1, b1i[2], b1i[3]);
                mma8(di[nn+1], fai1, b1r[2], b1r[3]);
                mma8(dr[nn+1], far1, b1r[2], b1r[3]);
                b1i[2] ^= 0x80000000u; b1i[3] ^= 0x80000000u;
                mma8(dr[nn+1], fai1, b1i[2], b1i[3]);
            }
        }
        __syncthreads();
        if (kk < 6){
            load_stage(xr, xi, st, m0, blk, n0, (kk + 2)*32, tid);
            cp_commit();
        }
    }

    // epilogue: bias + coalesced float2 stores
    float* o_r = out;
    float* o_i = out + OUT_HALF;
    int row0 = m0 + wid*16 + g;
    #pragma unroll
    for (int nn = 0; nn < 8; nn++){
        int cidx = n0 + nn*8 + 2*t;
        size_t col = (size_t)blk*CH + cidx;
        float b0r = bs[cidx], b1r = bs[cidx+1];
        float b0i = bs[256+cidx], b1i = bs[256+cidx+1];
        size_t a0 = (size_t)row0 * ROWSTRIDE + col;
        size_t a1 = (size_t)(row0 + 8) * ROWSTRIDE + col;
        float2 v;
        v.x = dr[nn][0] + b0r; v.y = dr[nn][1] + b1r;
        *(float2*)(o_r + a0) = v;
        v.x = dr[nn][2] + b0r; v.y = dr[nn][3] + b1r;
        *(float2*)(o_r + a1) = v;
        v.x = di[nn][0] + b0i; v.y = di[nn][1] + b1i;
        *(float2*)(o_i + a0) = v;
        v.x = di[nn][2] + b0i; v.y = di[nn][3] + b1i;
        *(float2*)(o_i + a1) = v;
    }
}

// ---------------------------------------------------------------------------
extern "C" void kernel_launch(void* const* d_in, const int* in_sizes, int n_in,
                              void* d_out, int out_size)
{
    const float* real = (const float*)d_in[0];
    const float* imag = (const float*)d_in[1];
    const float* w_r  = (const float*)d_in[2];
    const float* w_i  = (const float*)d_in[3];
    const float* b_r  = (const float*)d_in[4];
    const float* b_i  = (const float*)d_in[5];
    float* out = (float*)d_out;

    cudaFuncSetAttribute(emm_main,
        cudaFuncAttributeMaxDynamicSharedMemorySize, SMEM_ALLOC);

    emm_prep<<<dim3(8, 8, 16), dim3(32, 8)>>>(w_r, w_i);
    emm_main<<<dim3(512, 8), 256, SMEM_ALLOC>>>(real, imag, b_r, b_i, out);
}

// round 5
// speedup vs baseline: 1.6418x; 1.6418x over previous
#include <cuda_runtime.h>
#include <cuda_fp16.h>
#include <cstdint>

#define NBLK 8
#define CH 256
#define ROWSTRIDE 2048
#define OUT_HALF 33554432u

// stage: A_r 16KB | A_i 16KB | W_r 4KB | W_i 4KB = 40KB
#define OFF_AR 0
#define OFF_AI 16384
#define OFF_WR 32768
#define OFF_WI 36864
#define STAGE_BYTES 40960
#define SMEM_ST0  2048
#define SMEM_ALLOC (2048 + 2*STAGE_BYTES)   // 83968 -> 2 CTA/SM

#define NSIGN 0x80008000u

// weights fp16, per (sel,blk,n): 256 k permuted in 32-chunks so one lane's
// stage fragment (k pairs 2t,2t+1,2t+8,2t+9, both 16-halves) is 16 contiguous B
__device__ __half g_wT[2*NBLK*CH*CH];

// ---------------------------------------------------------------------------
__device__ __forceinline__ uint32_t smem_u32(const void* p){
    uint32_t r;
    asm("{ .reg .u64 t; cvta.to.shared.u64 t, %1; cvt.u32.u64 %0, t; }"
        : "=r"(r) : "l"(p));
    return r;
}
__device__ __forceinline__ void cpa16(uint32_t dst, const void* src){
    asm volatile("cp.async.cg.shared.global [%0], [%1], 16;"
                 :: "r"(dst), "l"(src) : "memory");
}
__device__ __forceinline__ void cp_commit(){ asm volatile("cp.async.commit_group;" ::: "memory"); }
__device__ __forceinline__ void cp_wait1(){ asm volatile("cp.async.wait_group 1;" ::: "memory"); }
__device__ __forceinline__ void cp_wait0(){ asm volatile("cp.async.wait_group 0;" ::: "memory"); }

__device__ __forceinline__ float2 lds64(uint32_t a){
    float2 v; asm volatile("ld.shared.v2.f32 {%0,%1}, [%2];"
        : "=f"(v.x), "=f"(v.y) : "r"(a)); return v;
}
__device__ __forceinline__ void lds128(uint32_t a, uint32_t* v){
    asm volatile("ld.shared.v4.b32 {%0,%1,%2,%3}, [%4];"
        : "=r"(v[0]), "=r"(v[1]), "=r"(v[2]), "=r"(v[3]) : "r"(a));
}
__device__ __forceinline__ uint32_t packh2(float2 v){
    __half2 h = __floats2half2_rn(v.x, v.y);        // lo = v.x (even k)
    return *(uint32_t*)&h;
}
__device__ __forceinline__ void mma16(float* d, const uint32_t* a,
                                      uint32_t b0, uint32_t b1){
    asm volatile(
        "mma.sync.aligned.m16n8k16.row.col.f32.f16.f16.f32 "
        "{%0,%1,%2,%3}, {%4,%5,%6,%7}, {%8,%9}, {%0,%1,%2,%3};"
        : "+f"(d[0]), "+f"(d[1]), "+f"(d[2]), "+f"(d[3])
        : "r"(a[0]), "r"(a[1]), "r"(a[2]), "r"(a[3]), "r"(b0), "r"(b1));
}

// fragment permutation within a 32-k chunk
__device__ __forceinline__ int p32(int k){
    int t = (k >> 1) & 3;
    int j = (k & 1) + (((k >> 3) & 1) << 1);
    int s = k >> 4;
    return t*8 + s*4 + j;
}

// ---------------------------------------------------------------------------
// Prep: w[b][d][n] fp32 -> g_wT[sel][b][n][(d&~31) + p32(d&31)] fp16
// ---------------------------------------------------------------------------
__global__ void emm_prep(const float* __restrict__ wr, const float* __restrict__ wi){
    __shared__ float tile[32][33];
    int bb = blockIdx.z;                 // sel*8 + b
    const float* s = (bb >= 8 ? wi : wr) + (size_t)(bb & 7)*CH*CH;
    __half* dst = g_wT + (size_t)bb*CH*CH;
    int d0 = blockIdx.x*32, n0 = blockIdx.y*32;
    int tx = threadIdx.x, ty = threadIdx.y;
    #pragma unroll
    for (int i = 0; i < 32; i += 8)
        tile[ty+i][tx] = s[(size_t)(d0+ty+i)*CH + (n0+tx)];   // [d][n]
    __syncthreads();
    int p = d0 + p32(tx);
    #pragma unroll
    for (int i = 0; i < 32; i += 8)
        dst[(size_t)(n0+ty+i)*CH + p] = __float2half_rn(tile[tx][ty+i]);
}

// ---------------------------------------------------------------------------
// Stage load: A 128x32 fp32 (r,i) swizzled; W 64x32 fp16 permuted (r,i)
// ---------------------------------------------------------------------------
__device__ __forceinline__ void load_stage(
    const float* __restrict__ xr, const float* __restrict__ xi,
    uint32_t st, int m0, int blk, int n0, int k0, int tid)
{
    #pragma unroll
    for (int i = 0; i < 4; i++){            // A: 1024 chunks per tensor
        int c = tid + i*256;
        int row = c >> 3, cc = c & 7;
        uint32_t d = st + (uint32_t)(row*128 + ((cc ^ (row & 7))*16));
        size_t gg = (size_t)(m0 + row)*ROWSTRIDE + blk*CH + k0 + cc*4;
        cpa16(d + OFF_AR, xr + gg);
        cpa16(d + OFF_AI, xi + gg);
    }
    {                                        // W: 256 chunks per tensor
        int n = tid >> 2, c = tid & 3;
        size_t hidx = ((size_t)blk*CH + n0 + n)*CH + (size_t)(k0 & ~31);
        const char* wrp = (const char*)g_wT + hidx*2 + c*16;
        const char* wip = wrp + (size_t)NBLK*CH*CH*2;
        uint32_t d = st + (uint32_t)(n*64 + c*16);
        cpa16(d + OFF_WR, wrp);
        cpa16(d + OFF_WI, wip);
    }
}

// ---------------------------------------------------------------------------
__global__ void __launch_bounds__(256, 2) emm_main(
    const float* __restrict__ xr, const float* __restrict__ xi,
    const float* __restrict__ br, const float* __restrict__ bi,
    float* __restrict__ out)
{
    extern __shared__ char smem[];
    uint32_t sb = smem_u32(smem);
    int tid = threadIdx.x;
    int wid = tid >> 5, lid = tid & 31;
    int g = lid >> 2, t = lid & 3;

    int bx = blockIdx.x;
    int m0 = (bx >> 2) * 128;
    int n0 = (bx & 3) * 64;
    int blk = blockIdx.y;

    float* bs = (float*)smem;               // bias: 512 floats
    bs[tid]       = br[blk*CH + tid];
    bs[tid + 256] = bi[blk*CH + tid];

    uint32_t st0 = sb + SMEM_ST0;
    uint32_t st1 = st0 + STAGE_BYTES;

    float dr[8][4], di[8][4];
    #pragma unroll
    for (int n = 0; n < 8; n++)
        #pragma unroll
        for (int c = 0; c < 4; c++){ dr[n][c] = 0.f; di[n][c] = 0.f; }

    load_stage(xr, xi, st0, m0, blk, n0, 0,  tid); cp_commit();
    load_stage(xr, xi, st1, m0, blk, n0, 32, tid); cp_commit();

    int rA = wid*16 + g;
    uint32_t abase = (uint32_t)(rA*128 + (t & 1)*8);
    // swizzled 16B-chunk offsets: s in {0,1}, j in {0,1} (k pair 2t / 2t+8)
    uint32_t o00 = (uint32_t)(((0*4 + (t>>1) + 0) ^ g) << 4);
    uint32_t o01 = (uint32_t)(((0*4 + (t>>1) + 2) ^ g) << 4);
    uint32_t o10 = (uint32_t)(((1*4 + (t>>1) + 0) ^ g) << 4);
    uint32_t o11 = (uint32_t)(((1*4 + (t>>1) + 2) ^ g) << 4);
    uint32_t wfrag = (uint32_t)(g*64 + t*16);

    #pragma unroll 1
    for (int kk = 0; kk < 8; kk++){
        uint32_t st = (kk & 1) ? st1 : st0;
        if (kk == 7) cp_wait0(); else cp_wait1();
        __syncthreads();

        uint32_t aR = st + OFF_AR + abase;
        uint32_t aI = st + OFF_AI + abase;

        uint32_t far0[4], fai0[4], far1[4], fai1[4];
        far0[0] = packh2(lds64(aR + o00));
        far0[1] = packh2(lds64(aR + o00 + 1024));
        far0[2] = packh2(lds64(aR + o01));
        far0[3] = packh2(lds64(aR + o01 + 1024));
        fai0[0] = packh2(lds64(aI + o00));
        fai0[1] = packh2(lds64(aI + o00 + 1024));
        fai0[2] = packh2(lds64(aI + o01));
        fai0[3] = packh2(lds64(aI + o01 + 1024));
        far1[0] = packh2(lds64(aR + o10));
        far1[1] = packh2(lds64(aR + o10 + 1024));
        far1[2] = packh2(lds64(aR + o11));
        far1[3] = packh2(lds64(aR + o11 + 1024));
        fai1[0] = packh2(lds64(aI + o10));
        fai1[1] = packh2(lds64(aI + o10 + 1024));
        fai1[2] = packh2(lds64(aI + o11));
        fai1[3] = packh2(lds64(aI + o11 + 1024));

        uint32_t wR = st + OFF_WR + wfrag;
        uint32_t wI = st + OFF_WI + wfrag;

        #pragma unroll
        for (int nn = 0; nn < 8; nn += 2){
            uint32_t br0[4], bi0[4], br1[4], bi1[4];
            lds128(wR + nn*512,       br0);
            lds128(wI + nn*512,       bi0);
            lds128(wR + nn*512 + 512, br1);
            lds128(wI + nn*512 + 512, bi1);
            // ---- s = 0 (regs [0],[1]) ----
            mma16(di[nn],   far0, bi0[0], bi0[1]);
            mma16(di[nn+1], far0, bi1[0], bi1[1]);
            mma16(dr[nn],   far0, br0[0], br0[1]);
            mma16(dr[nn+1], far0, br1[0], br1[1]);
            bi0[0] ^= NSIGN; bi0[1] ^= NSIGN;
            bi1[0] ^= NSIGN; bi1[1] ^= NSIGN;
            mma16(dr[nn],   fai0, bi0[0], bi0[1]);
            mma16(dr[nn+1], fai0, bi1[0], bi1[1]);
            mma16(di[nn],   fai0, br0[0], br0[1]);
            mma16(di[nn+1], fai0, br1[0], br1[1]);
            // ---- s = 1 (regs [2],[3]) ----
            mma16(di[nn],   far1, bi0[2], bi0[3]);
            mma16(di[nn+1], far1, bi1[2], bi1[3]);
            mma16(dr[nn],   far1, br0[2], br0[3]);
            mma16(dr[nn+1], far1, br1[2], br1[3]);
            bi0[2] ^= NSIGN; bi0[3] ^= NSIGN;
            bi1[2] ^= NSIGN; bi1[3] ^= NSIGN;
            mma16(dr[nn],   fai1, bi0[2], bi0[3]);
            mma16(dr[nn+1], fai1, bi1[2], bi1[3]);
            mma16(di[nn],   fai1, br0[2], br0[3]);
            mma16(di[nn+1], fai1, br1[2], br1[3]);
        }
        __syncthreads();
        if (kk < 6){
            load_stage(xr, xi, st, m0, blk, n0, (kk + 2)*32, tid);
            cp_commit();
        }
    }

    // epilogue: bias + coalesced float2 stores
    float* o_r = out;
    float* o_i = out + OUT_HALF;
    int row0 = m0 + wid*16 + g;
    #pragma unroll
    for (int nn = 0; nn < 8; nn++){
        int cidx = n0 + nn*8 + 2*t;
        size_t col = (size_t)blk*CH + cidx;
        float b0r = bs[cidx], b1r = bs[cidx+1];
        float b0i = bs[256+cidx], b1i = bs[256+cidx+1];
        size_t a0 = (size_t)row0 * ROWSTRIDE + col;
        size_t a1 = (size_t)(row0 + 8) * ROWSTRIDE + col;
        float2 v;
        v.x = dr[nn][0] + b0r; v.y = dr[nn][1] + b1r;
        *(float2*)(o_r + a0) = v;
        v.x = dr[nn][2] + b0r; v.y = dr[nn][3] + b1r;
        *(float2*)(o_r + a1) = v;
        v.x = di[nn][0] + b0i; v.y = di[nn][1] + b1i;
        *(float2*)(o_i + a0) = v;
        v.x = di[nn][2] + b0i; v.y = di[nn][3] + b1i;
        *(float2*)(o_i + a1) = v;
    }
}

// ---------------------------------------------------------------------------
extern "C" void kernel_launch(void* const* d_in, const int* in_sizes, int n_in,
                              void* d_out, int out_size)
{
    const float* real = (const float*)d_in[0];
    const float* imag = (const float*)d_in[1];
    const float* w_r  = (const float*)d_in[2];
    const float* w_i  = (const float*)d_in[3];
    const float* b_r  = (const float*)d_in[4];
    const float* b_i  = (const float*)d_in[5];
    float* out = (float*)d_out;

    cudaFuncSetAttribute(emm_main,
        cudaFuncAttributeMaxDynamicSharedMemorySize, SMEM_ALLOC);

    emm_prep<<<dim3(8, 8, 16), dim3(32, 8)>>>(w_r, w_i);
    emm_main<<<dim3(512, 8), 256, SMEM_ALLOC>>>(real, imag, b_r, b_i, out);
}

// round 7
// speedup vs baseline: 1.9167x; 1.1675x over previous
#include <cuda_runtime.h>
#include <cuda_fp16.h>
#include <cstdint>

#define NBLK 8
#define CH 256
#define ROWSTRIDE 2048
#define OUT_HALF 33554432u

#define NSIGN 0x80008000u

// smem: bias 2KB | W_r 34816B (32 rows x 1088) | W_i 34816B
#define SMEM_BIAS 0
#define SMEM_WR   2048
#define SMEM_WI   (2048 + 34816)
#define SMEM_ALLOC (2048 + 2*34816)      // 71680 -> 2 CTA/SM (regs are the cap)

// fp16 weights, fragment-permuted per (sel,blk):
// byte offset = rowg*1024 + s*64 + t*16 + h*8 + j*2
//   n = (rowg>>3)*16 + h*8 + (rowg&7),  k = s*16 + t*4 + j
__device__ __half g_wT[2*NBLK*CH*CH];

// ---------------------------------------------------------------------------
__device__ __forceinline__ uint32_t smem_u32(const void* p){
    uint32_t r;
    asm("{ .reg .u64 t; cvta.to.shared.u64 t, %1; cvt.u32.u64 %0, t; }"
        : "=r"(r) : "l"(p));
    return r;
}
__device__ __forceinline__ void cpa16(uint32_t dst, const void* src){
    asm volatile("cp.async.cg.shared.global [%0], [%1], 16;"
                 :: "r"(dst), "l"(src) : "memory");
}
__device__ __forceinline__ void cp_commit(){ asm volatile("cp.async.commit_group;" ::: "memory"); }
__device__ __forceinline__ void cp_wait0(){ asm volatile("cp.async.wait_group 0;" ::: "memory"); }

__device__ __forceinline__ void lds128(uint32_t a, uint32_t* v){
    asm volatile("ld.shared.v4.b32 {%0,%1,%2,%3}, [%4];"
        : "=r"(v[0]), "=r"(v[1]), "=r"(v[2]), "=r"(v[3]) : "r"(a));
}
__device__ __forceinline__ uint32_t packh2(float x, float y){
    __half2 h = __floats2half2_rn(x, y);
    return *(uint32_t*)&h;
}
__device__ __forceinline__ void mma16(float* d, const uint32_t* a,
                                      uint32_t b0, uint32_t b1){
    asm volatile(
        "mma.sync.aligned.m16n8k16.row.col.f32.f16.f16.f32 "
        "{%0,%1,%2,%3}, {%4,%5,%6,%7}, {%8,%9}, {%0,%1,%2,%3};"
        : "+f"(d[0]), "+f"(d[1]), "+f"(d[2]), "+f"(d[3])
        : "r"(a[0]), "r"(a[1]), "r"(a[2]), "r"(a[3]), "r"(b0), "r"(b1));
}

// ---------------------------------------------------------------------------
// Prep: w[b][d][n] fp32 -> g_wT permuted fp16 (layout above)
// grid (16 bb, 16 s) x 256 threads: coalesced reads, scattered 8B writes
// ---------------------------------------------------------------------------
__global__ void emm_prep(const float* __restrict__ wr, const float* __restrict__ wi){
    int bb = blockIdx.x;                 // sel*8 + b
    int s  = blockIdx.y;                 // k-slice 0..15
    const float* src = (bb >= 8 ? wi : wr) + (size_t)(bb & 7)*CH*CH;
    char* dst = (char*)g_wT + (size_t)bb*CH*CH*2;
    int n = threadIdx.x;                 // 0..255
    int rowg = (n >> 4)*8 + (n & 7);
    int h = (n >> 3) & 1;
    #pragma unroll
    for (int t = 0; t < 4; t++){
        int d = s*16 + t*4;
        uint2 v;
        v.x = packh2(src[(size_t)d*CH + n],     src[(size_t)(d+1)*CH + n]);
        v.y = packh2(src[(size_t)(d+2)*CH + n], src[(size_t)(d+3)*CH + n]);
        *(uint2*)(dst + rowg*1024 + s*64 + t*16 + h*8) = v;
    }
}

// ---------------------------------------------------------------------------
__global__ void __launch_bounds__(256, 2) emm_main(
    const float* __restrict__ xr, const float* __restrict__ xi,
    const float* __restrict__ br, const float* __restrict__ bi,
    float* __restrict__ out)
{
    extern __shared__ char smem[];
    uint32_t sb = smem_u32(smem);
    int tid = threadIdx.x;
    int wid = tid >> 5, lid = tid & 31;
    int g = lid >> 2, t = lid & 3;

    int bx = blockIdx.x;
    int m0 = (bx >> 2) * 128;            // adjacent bx share m0 -> L2 reuse
    int n0 = (bx & 3) * 64;
    int blk = blockIdx.y;

    // A row pointers for this lane (rows rA and rA+8, k chunk t*4)
    const float* pr0 = xr + (size_t)(m0 + wid*16 + g)*ROWSTRIDE + blk*CH + t*4;
    const float* pr1 = pr0 + 8*ROWSTRIDE;
    const float* pi0 = xi + (size_t)(m0 + wid*16 + g)*ROWSTRIDE + blk*CH + t*4;
    const float* pi1 = pi0 + 8*ROWSTRIDE;

    // kick off slice 0 A loads early (hide behind W smem fill)
    float4 rawR[2][2], rawI[2][2];
    rawR[0][0] = *(const float4*)pr0;
    rawR[0][1] = *(const float4*)pr1;
    rawI[0][0] = *(const float4*)pi0;
    rawI[0][1] = *(const float4*)pi1;

    // bias -> smem
    float* bs = (float*)smem;
    bs[tid]       = br[blk*CH + tid];
    bs[tid + 256] = bi[blk*CH + tid];

    // W -> smem once: exactly 2048 16B chunks per tensor (32KB source),
    // rows of 64 chunks padded 1024 -> 1088 bytes in smem
    {
        const char* wr_src = (const char*)g_wT + (size_t)blk*131072 + (size_t)n0*512;
        const char* wi_src = wr_src + (size_t)NBLK*131072;
        #pragma unroll
        for (int i = 0; i < 8; i++){
            int c = tid + i*256;         // 0..2047
            uint32_t d = (uint32_t)((c >> 6)*1088 + (c & 63)*16);
            cpa16(sb + SMEM_WR + d, wr_src + (size_t)c*16);
            cpa16(sb + SMEM_WI + d, wi_src + (size_t)c*16);
        }
        cp_commit();
    }

    float dr[8][4], di[8][4];
    #pragma unroll
    for (int n = 0; n < 8; n++)
        #pragma unroll
        for (int c = 0; c < 4; c++){ dr[n][c] = 0.f; di[n][c] = 0.f; }

    cp_wait0();
    __syncthreads();                     // the ONLY barrier before epilogue

    uint32_t wr_a = sb + SMEM_WR + (uint32_t)(g*1088 + t*16);
    uint32_t wi_a = sb + SMEM_WI + (uint32_t)(g*1088 + t*16);

    #pragma unroll
    for (int j = 0; j < 16; j++){        // 16 k-slices of 16
        int cur = j & 1, nxt = cur ^ 1;
        if (j < 15){
            int o = (j + 1) * 16;
            rawR[nxt][0] = *(const float4*)(pr0 + o);
            rawR[nxt][1] = *(const float4*)(pr1 + o);
            rawI[nxt][0] = *(const float4*)(pi0 + o);
            rawI[nxt][1] = *(const float4*)(pi1 + o);
        }
        uint32_t far[4], fai[4];
        far[0] = packh2(rawR[cur][0].x, rawR[cur][0].y);
        far[1] = packh2(rawR[cur][1].x, rawR[cur][1].y);
        far[2] = packh2(rawR[cur][0].z, rawR[cur][0].w);
        far[3] = packh2(rawR[cur][1].z, rawR[cur][1].w);
        fai[0] = packh2(rawI[cur][0].x, rawI[cur][0].y);
        fai[1] = packh2(rawI[cur][1].x, rawI[cur][1].y);
        fai[2] = packh2(rawI[cur][0].z, rawI[cur][0].w);
        fai[3] = packh2(rawI[cur][1].z, rawI[cur][1].w);

        uint32_t wro = wr_a + j*64;
        uint32_t wio = wi_a + j*64;
        #pragma unroll
        for (int q = 0; q < 4; q++){     // nn pair (2q, 2q+1)
            uint32_t brv[4], biv[4];
            lds128(wro + q*8704, brv);   // [b0 b1 nn_lo | b0 b1 nn_hi]
            lds128(wio + q*8704, biv);
            mma16(di[2*q],   far, biv[0], biv[1]);
            mma16(di[2*q+1], far, biv[2], biv[3]);
            mma16(dr[2*q],   far, brv[0], brv[1]);
            mma16(dr[2*q+1], far, brv[2], brv[3]);
            mma16(di[2*q],   fai, brv[0], brv[1]);
            mma16(di[2*q+1], fai, brv[2], brv[3]);
            biv[0] ^= NSIGN; biv[1] ^= NSIGN;
            biv[2] ^= NSIGN; biv[3] ^= NSIGN;
            mma16(dr[2*q],   fai, biv[0], biv[1]);
            mma16(dr[2*q+1], fai, biv[2], biv[3]);
        }
    }

    // epilogue: bias + coalesced float2 stores
    float* o_r = out;
    float* o_i = out + OUT_HALF;
    int row0 = m0 + wid*16 + g;
    #pragma unroll
    for (int nn = 0; nn < 8; nn++){
        int cidx = n0 + nn*8 + 2*t;
        size_t col = (size_t)blk*CH + cidx;
        float b0r = bs[cidx], b1r = bs[cidx+1];
        float b0i = bs[256+cidx], b1i = bs[256+cidx+1];
        size_t a0 = (size_t)row0 * ROWSTRIDE + col;
        size_t a1 = (size_t)(row0 + 8) * ROWSTRIDE + col;
        float2 v;
        v.x = dr[nn][0] + b0r; v.y = dr[nn][1] + b1r;
        *(float2*)(o_r + a0) = v;
        v.x = dr[nn][2] + b0r; v.y = dr[nn][3] + b1r;
        *(float2*)(o_r + a1) = v;
        v.x = di[nn][0] + b0i; v.y = di[nn][1] + b1i;
        *(float2*)(o_i + a0) = v;
        v.x = di[nn][2] + b0i; v.y = di[nn][3] + b1i;
        *(float2*)(o_i + a1) = v;
    }
}

// ---------------------------------------------------------------------------
extern "C" void kernel_launch(void* const* d_in, const int* in_sizes, int n_in,
                              void* d_out, int out_size)
{
    const float* real = (const float*)d_in[0];
    const float* imag = (const float*)d_in[1];
    const float* w_r  = (const float*)d_in[2];
    const float* w_i  = (const float*)d_in[3];
    const float* b_r  = (const float*)d_in[4];
    const float* b_i  = (const float*)d_in[5];
    float* out = (float*)d_out;

    cudaFuncSetAttribute(emm_main,
        cudaFuncAttributeMaxDynamicSharedMemorySize, SMEM_ALLOC);

    emm_prep<<<dim3(16, 16), 256>>>(w_r, w_i);
    emm_main<<<dim3(512, 8), 256, SMEM_ALLOC>>>(real, imag, b_r, b_i, out);
}

// round 8
// speedup vs baseline: 1.9653x; 1.0253x over previous
#include <cuda_runtime.h>
#include <cuda_fp16.h>
#include <cstdint>

#define NBLK 8
#define CH 256
#define ROWSTRIDE 2048
#define OUT_HALF 33554432u

#define NSIGN 0x80008000u

// smem: bias 2KB | W_r 34816B (32 rows x 1088) | W_i 34816B
#define SMEM_WR   2048
#define SMEM_WI   (2048 + 34816)
#define SMEM_ALLOC (2048 + 2*34816)      // 71680 -> 2 CTA/SM

// fp16 weights, fragment-permuted per (sel,blk):
// byte offset = rowg*1024 + s*64 + t*16 + h*8 + j*2
//   n = (rowg>>3)*16 + h*8 + (rowg&7),  k = s*16 + t*4 + j
__device__ __half g_wT[2*NBLK*CH*CH];

// ---------------------------------------------------------------------------
__device__ __forceinline__ uint32_t smem_u32(const void* p){
    uint32_t r;
    asm("{ .reg .u64 t; cvta.to.shared.u64 t, %1; cvt.u32.u64 %0, t; }"
        : "=r"(r) : "l"(p));
    return r;
}
__device__ __forceinline__ void cpa16(uint32_t dst, const void* src){
    asm volatile("cp.async.cg.shared.global [%0], [%1], 16;"
                 :: "r"(dst), "l"(src) : "memory");
}
__device__ __forceinline__ void cp_commit(){ asm volatile("cp.async.commit_group;" ::: "memory"); }
__device__ __forceinline__ void cp_wait0(){ asm volatile("cp.async.wait_group 0;" ::: "memory"); }

__device__ __forceinline__ void lds128(uint32_t a, uint32_t* v){
    asm volatile("ld.shared.v4.b32 {%0,%1,%2,%3}, [%4];"
        : "=r"(v[0]), "=r"(v[1]), "=r"(v[2]), "=r"(v[3]) : "r"(a));
}
__device__ __forceinline__ uint32_t packh2(float x, float y){
    __half2 h = __floats2half2_rn(x, y);
    return *(uint32_t*)&h;
}
__device__ __forceinline__ void mma16(float* d, const uint32_t* a,
                                      uint32_t b0, uint32_t b1){
    asm volatile(
        "mma.sync.aligned.m16n8k16.row.col.f32.f16.f16.f32 "
        "{%0,%1,%2,%3}, {%4,%5,%6,%7}, {%8,%9}, {%0,%1,%2,%3};"
        : "+f"(d[0]), "+f"(d[1]), "+f"(d[2]), "+f"(d[3])
        : "r"(a[0]), "r"(a[1]), "r"(a[2]), "r"(a[3]), "r"(b0), "r"(b1));
}

// ---------------------------------------------------------------------------
// Prep: w[b][d][n] fp32 -> g_wT permuted fp16
// ---------------------------------------------------------------------------
__global__ void emm_prep(const float* __restrict__ wr, const float* __restrict__ wi){
    int bb = blockIdx.x;                 // sel*8 + b
    int s  = blockIdx.y;                 // k-slice 0..15
    const float* src = (bb >= 8 ? wi : wr) + (size_t)(bb & 7)*CH*CH;
    char* dst = (char*)g_wT + (size_t)bb*CH*CH*2;
    int n = threadIdx.x;                 // 0..255
    int rowg = (n >> 4)*8 + (n & 7);
    int h = (n >> 3) & 1;
    #pragma unroll
    for (int t = 0; t < 4; t++){
        int d = s*16 + t*4;
        uint2 v;
        v.x = packh2(src[(size_t)d*CH + n],     src[(size_t)(d+1)*CH + n]);
        v.y = packh2(src[(size_t)(d+2)*CH + n], src[(size_t)(d+3)*CH + n]);
        *(uint2*)(dst + rowg*1024 + s*64 + t*16 + h*8) = v;
    }
}

// ---------------------------------------------------------------------------
__global__ void __launch_bounds__(256, 2) emm_main(
    const float* __restrict__ xr, const float* __restrict__ xi,
    const float* __restrict__ br, const float* __restrict__ bi,
    float* __restrict__ out)
{
    extern __shared__ char smem[];
    uint32_t sb = smem_u32(smem);
    int tid = threadIdx.x;
    int wid = tid >> 5, lid = tid & 31;
    int g = lid >> 2, t = lid & 3;

    int bx = blockIdx.x;
    int m0 = (bx >> 2) * 128;            // adjacent bx share m0 -> L2 reuse
    int n0 = (bx & 3) * 64;
    int blk = blockIdx.y;

    const float* pr0 = xr + (size_t)(m0 + wid*16 + g)*ROWSTRIDE + blk*CH + t*4;
    const float* pr1 = pr0 + 8*ROWSTRIDE;
    const float* pi0 = xi + (size_t)(m0 + wid*16 + g)*ROWSTRIDE + blk*CH + t*4;
    const float* pi1 = pi0 + 8*ROWSTRIDE;

    // slice-0 A loads (hide behind W smem fill)
    float4 rR0 = *(const float4*)pr0;
    float4 rR1 = *(const float4*)pr1;
    float4 rI0 = *(const float4*)pi0;
    float4 rI1 = *(const float4*)pi1;

    // bias -> smem
    float* bs = (float*)smem;
    bs[tid]       = br[blk*CH + tid];
    bs[tid + 256] = bi[blk*CH + tid];

    // W -> smem once: 2048 16B chunks per tensor, rows padded 1024 -> 1088
    {
        const char* wr_src = (const char*)g_wT + (size_t)blk*131072 + (size_t)n0*512;
        const char* wi_src = wr_src + (size_t)NBLK*131072;
        #pragma unroll
        for (int i = 0; i < 8; i++){
            int c = tid + i*256;         // 0..2047
            uint32_t d = (uint32_t)((c >> 6)*1088 + (c & 63)*16);
            cpa16(sb + SMEM_WR + d, wr_src + (size_t)c*16);
            cpa16(sb + SMEM_WI + d, wi_src + (size_t)c*16);
        }
        cp_commit();
    }

    float dr[8][4], di[8][4];
    #pragma unroll
    for (int n = 0; n < 8; n++)
        #pragma unroll
        for (int c = 0; c < 4; c++){ dr[n][c] = 0.f; di[n][c] = 0.f; }

    cp_wait0();
    __syncthreads();                     // the ONLY barrier before epilogue

    // pack slice-0 fragments, compute fan = -fai
    uint32_t far[4], fai[4], fan[4];
    far[0] = packh2(rR0.x, rR0.y); far[1] = packh2(rR1.x, rR1.y);
    far[2] = packh2(rR0.z, rR0.w); far[3] = packh2(rR1.z, rR1.w);
    fai[0] = packh2(rI0.x, rI0.y); fai[1] = packh2(rI1.x, rI1.y);
    fai[2] = packh2(rI0.z, rI0.w); fai[3] = packh2(rI1.z, rI1.w);
    fan[0] = fai[0]^NSIGN; fan[1] = fai[1]^NSIGN;
    fan[2] = fai[2]^NSIGN; fan[3] = fai[3]^NSIGN;

    // issue slice-1 A loads
    rR0 = *(const float4*)(pr0 + 16); rR1 = *(const float4*)(pr1 + 16);
    rI0 = *(const float4*)(pi0 + 16); rI1 = *(const float4*)(pi1 + 16);

    uint32_t wro = sb + SMEM_WR + (uint32_t)(g*1088 + t*16);
    uint32_t wio = sb + SMEM_WI + (uint32_t)(g*1088 + t*16);

    // preload W fragments for (j=0, q=0)
    uint32_t wfr[2][4], wfi[2][4];
    lds128(wro, wfr[0]);
    lds128(wio, wfi[0]);

    #pragma unroll 1
    for (int j = 0; j < 16; j++){
        #pragma unroll
        for (int q = 0; q < 4; q++){
            int cur = q & 1, nx = cur ^ 1;
            if (q < 3){
                lds128(wro + (q+1)*8704, wfr[nx]);
                lds128(wio + (q+1)*8704, wfi[nx]);
            } else {
                lds128(wro + 64, wfr[nx]);   // next j, q=0
                lds128(wio + 64, wfi[nx]);
            }
            mma16(dr[2*q],   far, wfr[cur][0], wfr[cur][1]);
            mma16(dr[2*q+1], far, wfr[cur][2], wfr[cur][3]);
            mma16(di[2*q],   far, wfi[cur][0], wfi[cur][1]);
            mma16(di[2*q+1], far, wfi[cur][2], wfi[cur][3]);
            mma16(dr[2*q],   fan, wfi[cur][0], wfi[cur][1]);
            mma16(dr[2*q+1], fan, wfi[cur][2], wfi[cur][3]);
            mma16(di[2*q],   fai, wfr[cur][0], wfr[cur][1]);
            mma16(di[2*q+1], fai, wfr[cur][2], wfr[cur][3]);
        }
        wro += 64; wio += 64;
        if (j < 15){
            // pack next slice's fragments (LDG issued one slice ago)
            far[0] = packh2(rR0.x, rR0.y); far[1] = packh2(rR1.x, rR1.y);
            far[2] = packh2(rR0.z, rR0.w); far[3] = packh2(rR1.z, rR1.w);
            fai[0] = packh2(rI0.x, rI0.y); fai[1] = packh2(rI1.x, rI1.y);
            fai[2] = packh2(rI0.z, rI0.w); fai[3] = packh2(rI1.z, rI1.w);
            fan[0] = fai[0]^NSIGN; fan[1] = fai[1]^NSIGN;
            fan[2] = fai[2]^NSIGN; fan[3] = fai[3]^NSIGN;
            if (j < 14){
                int o = (j + 2) * 16;
                rR0 = *(const float4*)(pr0 + o);
                rR1 = *(const float4*)(pr1 + o);
                rI0 = *(const float4*)(pi0 + o);
                rI1 = *(const float4*)(pi1 + o);
            }
        }
    }

    // epilogue: bias + coalesced float2 stores
    float* o_r = out;
    float* o_i = out + OUT_HALF;
    int row0 = m0 + wid*16 + g;
    #pragma unroll
    for (int nn = 0; nn < 8; nn++){
        int cidx = n0 + nn*8 + 2*t;
        size_t col = (size_t)blk*CH + cidx;
        float b0r = bs[cidx], b1r = bs[cidx+1];
        float b0i = bs[256+cidx], b1i = bs[256+cidx+1];
        size_t a0 = (size_t)row0 * ROWSTRIDE + col;
        size_t a1 = (size_t)(row0 + 8) * ROWSTRIDE + col;
        float2 v;
        v.x = dr[nn][0] + b0r; v.y = dr[nn][1] + b1r;
        *(float2*)(o_r + a0) = v;
        v.x = dr[nn][2] + b0r; v.y = dr[nn][3] + b1r;
        *(float2*)(o_r + a1) = v;
        v.x = di[nn][0] + b0i; v.y = di[nn][1] + b1i;
        *(float2*)(o_i + a0) = v;
        v.x = di[nn][2] + b0i; v.y = di[nn][3] + b1i;
        *(float2*)(o_i + a1) = v;
    }
}

// ---------------------------------------------------------------------------
extern "C" void kernel_launch(void* const* d_in, const int* in_sizes, int n_in,
                              void* d_out, int out_size)
{
    const float* real = (const float*)d_in[0];
    const float* imag = (const float*)d_in[1];
    const float* w_r  = (const float*)d_in[2];
    const float* w_i  = (const float*)d_in[3];
    const float* b_r  = (const float*)d_in[4];
    const float* b_i  = (const float*)d_in[5];
    float* out = (float*)d_out;

    cudaFuncSetAttribute(emm_main,
        cudaFuncAttributeMaxDynamicSharedMemorySize, SMEM_ALLOC);

    emm_prep<<<dim3(16, 16), 256>>>(w_r, w_i);
    emm_main<<<dim3(512, 8), 256, SMEM_ALLOC>>>(real, imag, b_r, b_i, out);
}